// round 12
// baseline (speedup 1.0000x reference)
#include <cuda_runtime.h>

#define HIDDEN 8
#define RES 64
#define NBATCH 2048
#define TILE_H 16
#define SROWS 20           // TILE_H + 4 halo rows
#define SROW 72            // padded smem row stride (floats): cols 0..67 used
#define SP_FLOATS (HIDDEN * SROWS * SROW)      // 11520 floats, planar [ch][row][col]
// param sections (float offsets; keep 16B alignment for the ull/float4 parts)
#define OFF_SWT  (SP_FLOATS)             // conv weights, 8ch x 5r x 8 slots = 320 floats
#define OFF_SW2B (OFF_SWT + 320)         // 64 ull broadcast pairs = 128 floats
#define OFF_SW3B (OFF_SW2B + 128)        // 128 floats
#define OFF_SB1  (OFF_SW3B + 128)        // 8 floats
#define OFF_SB2P (OFF_SB1 + 8)           // 8 ull = 16 floats
#define OFF_SB3P (OFF_SB2P + 16)         // 16 floats
#define SMEM_FLOATS (OFF_SB3P + 16)
#define SMEM_BYTES (SMEM_FLOATS * 4)

typedef unsigned long long ull;

// D4-symmetrized, per-kernel-zero-mean 5x5 depthwise weights
__device__ float g_w[HIDDEN * 25];

__global__ void prep_weights_kernel(const float* __restrict__ filter1) {
    __shared__ float sw[HIDDEN * 25];
    int t = threadIdx.x;
    float wv = 0.f;
    int h = 0;
    if (t < 200) {
        h = t / 25;
        int idx = t % 25;
        int i = idx / 5, j = idx % 5;
        const float* f = filter1 + h * 25;
        float s = f[i*5 + j] + f[(4-i)*5 + j] + f[i*5 + (4-j)] + f[(4-i)*5 + (4-j)]
                + f[j*5 + i] + f[(4-j)*5 + i] + f[j*5 + (4-i)] + f[(4-j)*5 + (4-i)];
        wv = 0.125f * s;
        sw[t] = wv;
    }
    __syncthreads();
    if (t < 200) {
        float m = 0.f;
        #pragma unroll
        for (int k = 0; k < 25; k++) m += sw[h * 25 + k];
        g_w[t] = wv - m * (1.0f / 25.0f);
    }
}

// ---- packed f32x2 helpers ----
__device__ __forceinline__ ull pack2(float lo, float hi) {
    ull d; asm("mov.b64 %0, {%1, %2};" : "=l"(d) : "f"(lo), "f"(hi)); return d;
}
__device__ __forceinline__ void unpack2(ull d, float& lo, float& hi) {
    asm("mov.b64 {%0, %1}, %2;" : "=f"(lo), "=f"(hi) : "l"(d));
}
__device__ __forceinline__ ull fma2(ull a, ull b, ull c) {
    ull d; asm("fma.rn.f32x2 %0, %1, %2, %3;" : "=l"(d) : "l"(a), "l"(b), "l"(c)); return d;
}
__device__ __forceinline__ ull mul2(ull a, ull b) {
    ull d; asm("mul.rn.f32x2 %0, %1, %2;" : "=l"(d) : "l"(a), "l"(b)); return d;
}
__device__ __forceinline__ ull add2(ull a, ull b) {
    ull d; asm("add.rn.f32x2 %0, %1, %2;" : "=l"(d) : "l"(a), "l"(b)); return d;
}
// packed leaky_relu: 0.505*x + 0.495*|x|  (== x for x>0, 0.01x for x<0)
__device__ __forceinline__ ull lrelu2(ull x, ull c505, ull c495) {
    ull ax = x & 0x7FFFFFFF7FFFFFFFULL;
    return fma2(ax, c495, mul2(x, c505));
}
// scalar leaky_relu; fabsf folds into the FFMA operand modifier -> 2 instrs
__device__ __forceinline__ float lrelu(float x) {
    return fmaf(0.495f, fabsf(x), 0.505f * x);
}
__device__ __forceinline__ float tanh_fast(float x) {
    float y;
    asm("tanh.approx.f32 %0, %1;" : "=f"(y) : "f"(x));
    return y;
}

__global__ __launch_bounds__(256, 4)
void ca_fused_kernel(const float* __restrict__ psi,
                     const float* __restrict__ bias1,
                     const float* __restrict__ w2,
                     const float* __restrict__ b2,
                     const float* __restrict__ w3,
                     const float* __restrict__ b3,
                     float* __restrict__ out)
{
    extern __shared__ __align__(16) float sm[];
    float* sp   = sm;                      // planar psi tile, pixel x at col x+2
    float* swt  = sm + OFF_SWT;            // conv weights: [(ch*5+r)*8 + dx], dx<5 valid
    ull*   sw2b = (ull*)(sm + OFF_SW2B);   // [i*8+o] = (w2[o][i], w2[o][i])
    ull*   sw3b = (ull*)(sm + OFF_SW3B);   // [i*8+o] = (w3[o][i], w3[o][i])
    float* sb1  = sm + OFF_SB1;            // 8
    ull*   sb2p = (ull*)(sm + OFF_SB2P);   // [o] = (b2[o], b2[o])
    ull*   sb3p = (ull*)(sm + OFF_SB3P);   // [o] = (b3[o], b3[o])

    const int tid = threadIdx.x;
    const int b   = blockIdx.y;
    const int y0  = blockIdx.x * TILE_H;

    // ---- stage params ----
    // FIX (R11 bug): 320 slots but only 256 threads -> must be a strided loop,
    // otherwise swt[256..319] (channels 6-7 weights) stay uninitialized.
    for (int k = tid; k < 320; k += 256) {
        int cr = k >> 3, dx = k & 7;       // cr = ch*5 + r
        int ch = cr / 5, r = cr % 5;
        swt[k] = (dx < 5) ? g_w[ch * 25 + r * 5 + dx] : 0.f;
    }
    if (tid < 64) {
        int i = tid >> 3, o = tid & 7;
        float a2 = w2[o * 8 + i], a3 = w3[o * 8 + i];
        sw2b[tid] = pack2(a2, a2);
        sw3b[tid] = pack2(a3, a3);
    }
    if (tid < 8) {
        sb1[tid] = bias1[tid];
        float v2 = b2[tid], v3 = b3[tid];
        sb2p[tid] = pack2(v2, v2);
        sb3p[tid] = pack2(v3, v3);
    }

    // ---- zero the x-halo columns (cols 0,1,66,67) ----
    for (int k = tid; k < HIDDEN * SROWS * 4; k += 256) {
        int c  = k & 3;
        int rr = k >> 2;                    // ch*SROWS + r
        int col = (c < 2) ? c : (64 + c);   // 0,1,66,67
        sp[rr * SROW + col] = 0.f;
    }

    // ---- interior fill: float4 global loads, zero rows outside the image ----
    const float* pb = psi + (size_t)b * (HIDDEN * RES * RES);
    for (int k = tid; k < HIDDEN * SROWS * 16; k += 256) {
        int q  = k & 15;                     // float4 index within row
        int rr = k >> 4;                     // ch*SROWS + r
        int r  = rr % SROWS;
        int ch = rr / SROWS;
        int gy = y0 + r - 2;
        float4 v = make_float4(0.f, 0.f, 0.f, 0.f);
        if ((unsigned)gy < RES)
            v = *(const float4*)(pb + (ch * RES + gy) * RES + q * 4);
        float2* d = (float2*)(sp + rr * SROW + q * 4 + 2);   // col = x+2 (8B aligned)
        d[0] = make_float2(v.x, v.y);
        d[1] = make_float2(v.z, v.w);
    }
    __syncthreads();

    const ull C505 = pack2(0.505f, 0.505f);
    const ull C495 = pack2(0.495f, 0.495f);

    // Each thread: 4 x-pixels of ONE output row, all 8 channels.
    const int tx = tid & 15;
    const int ry = tid >> 4;     // output row within tile (0..15)
    const int x0 = tx << 2;      // output x base (0..60)

    // GEMM1 accumulators, pixel-pair packed; conv fused into the channel loop.
    ull z2[8][2];
    #pragma unroll
    for (int o = 0; o < 8; o++) { ull bv = sb2p[o]; z2[o][0] = bv; z2[o][1] = bv; }

    #pragma unroll
    for (int ch = 0; ch < 8; ch++) {
        float bv = sb1[ch];
        float a0 = bv, a1 = bv, a2 = bv, a3 = bv;

        const float* base = sp + (ch * SROWS + ry) * SROW + x0;  // col x0 == pixel x0-2
        const float* wch  = swt + ch * 40;
        #pragma unroll
        for (int r = 0; r < 5; r++) {
            float4 A = *(const float4*)(base + r * SROW);
            float4 B = *(const float4*)(base + r * SROW + 4);
            float4 W = *(const float4*)(wch + r * 8);
            float  w4 = wch[r * 8 + 4];
            a0 = fmaf(W.x, A.x, a0); a1 = fmaf(W.x, A.y, a1);
            a2 = fmaf(W.x, A.z, a2); a3 = fmaf(W.x, A.w, a3);
            a0 = fmaf(W.y, A.y, a0); a1 = fmaf(W.y, A.z, a1);
            a2 = fmaf(W.y, A.w, a2); a3 = fmaf(W.y, B.x, a3);
            a0 = fmaf(W.z, A.z, a0); a1 = fmaf(W.z, A.w, a1);
            a2 = fmaf(W.z, B.x, a2); a3 = fmaf(W.z, B.y, a3);
            a0 = fmaf(W.w, A.w, a0); a1 = fmaf(W.w, B.x, a1);
            a2 = fmaf(W.w, B.y, a2); a3 = fmaf(W.w, B.z, a3);
            a0 = fmaf(w4,  B.x, a0); a1 = fmaf(w4,  B.y, a1);
            a2 = fmaf(w4,  B.z, a2); a3 = fmaf(w4,  B.w, a3);
        }
        // leaky_relu + pack to pixel pairs
        ull v0 = pack2(lrelu(a0), lrelu(a1));
        ull v1 = pack2(lrelu(a2), lrelu(a3));

        // fused GEMM1 accumulation (packed): z2[o] += w2[o][ch] * v
        const ull* wrow = sw2b + ch * 8;
        #pragma unroll
        for (int o = 0; o < 8; o++) {
            ull w = wrow[o];
            z2[o][0] = fma2(w, v0, z2[o][0]);
            z2[o][1] = fma2(w, v1, z2[o][1]);
        }
    }

    // leaky_relu on z2 (packed)
    #pragma unroll
    for (int o = 0; o < 8; o++) {
        z2[o][0] = lrelu2(z2[o][0], C505, C495);
        z2[o][1] = lrelu2(z2[o][1], C505, C495);
    }

    // GEMM2 per output channel (only 2 live accumulators) + residual + tanh + store
    float* ob = out + (size_t)b * (HIDDEN * RES * RES);
    const int gy = y0 + ry;
    #pragma unroll
    for (int o = 0; o < 8; o++) {
        ull h0 = sb3p[o], h1 = h0;
        #pragma unroll
        for (int i = 0; i < 8; i++) {
            ull w = sw3b[i * 8 + o];
            h0 = fma2(w, z2[i][0], h0);
            h1 = fma2(w, z2[i][1], h1);
        }
        // residual psi from smem: col x0+2 is even -> 8B-aligned ull loads
        const ull* rp = (const ull*)(sp + (o * SROWS + ry + 2) * SROW + x0 + 2);
        h0 = add2(h0, rp[0]);
        h1 = add2(h1, rp[1]);
        float e0, e1, e2, e3;
        unpack2(h0, e0, e1);
        unpack2(h1, e2, e3);
        float4 res;
        res.x = tanh_fast(e0); res.y = tanh_fast(e1);
        res.z = tanh_fast(e2); res.w = tanh_fast(e3);
        *(float4*)(ob + (o * RES + gy) * RES + x0) = res;
    }
}

extern "C" void kernel_launch(void* const* d_in, const int* in_sizes, int n_in,
                              void* d_out, int out_size) {
    const float* psi     = (const float*)d_in[0];
    const float* filter1 = (const float*)d_in[1];
    const float* bias1   = (const float*)d_in[2];
    const float* w2      = (const float*)d_in[3];
    const float* b2      = (const float*)d_in[4];
    const float* w3      = (const float*)d_in[5];
    const float* b3      = (const float*)d_in[6];
    float* out = (float*)d_out;

    cudaFuncSetAttribute(ca_fused_kernel,
                         cudaFuncAttributeMaxDynamicSharedMemorySize, SMEM_BYTES);

    prep_weights_kernel<<<1, 256>>>(filter1);

    dim3 grid(RES / TILE_H, NBATCH);
    ca_fused_kernel<<<grid, 256, SMEM_BYTES>>>(psi, bias1, w2, b2, w3, b3, out);
}

// round 13
// speedup vs baseline: 1.2952x; 1.2952x over previous
#include <cuda_runtime.h>

#define HIDDEN 8
#define RES 64
#define NBATCH 2048
#define TILE_H 16
#define SROWS 20           // TILE_H + 4 halo rows
#define SROW 72            // padded smem row stride (floats): cols 0..67 used
#define SP_FLOATS (HIDDEN * SROWS * SROW)      // 11520 floats, planar [ch][row][col]
// param sections (float offsets; keep 16B alignment for the ull/float4 parts)
#define OFF_SWT  (SP_FLOATS)             // conv weights, 8ch x 5r x 8 slots = 320 floats
#define OFF_SW2B (OFF_SWT + 320)         // 64 ull broadcast pairs = 128 floats
#define OFF_SW3B (OFF_SW2B + 128)        // 128 floats
#define OFF_SB1  (OFF_SW3B + 128)        // 8 floats
#define OFF_SB2P (OFF_SB1 + 8)           // 8 ull = 16 floats
#define OFF_SB3P (OFF_SB2P + 16)         // 16 floats
#define SMEM_FLOATS (OFF_SB3P + 16)
#define SMEM_BYTES (SMEM_FLOATS * 4)

typedef unsigned long long ull;

// D4-symmetrized, per-kernel-zero-mean 5x5 depthwise weights
__device__ float g_w[HIDDEN * 25];

__global__ void prep_weights_kernel(const float* __restrict__ filter1) {
    __shared__ float sw[HIDDEN * 25];
    int t = threadIdx.x;
    float wv = 0.f;
    int h = 0;
    if (t < 200) {
        h = t / 25;
        int idx = t % 25;
        int i = idx / 5, j = idx % 5;
        const float* f = filter1 + h * 25;
        float s = f[i*5 + j] + f[(4-i)*5 + j] + f[i*5 + (4-j)] + f[(4-i)*5 + (4-j)]
                + f[j*5 + i] + f[(4-j)*5 + i] + f[j*5 + (4-i)] + f[(4-j)*5 + (4-i)];
        wv = 0.125f * s;
        sw[t] = wv;
    }
    __syncthreads();
    if (t < 200) {
        float m = 0.f;
        #pragma unroll
        for (int k = 0; k < 25; k++) m += sw[h * 25 + k];
        g_w[t] = wv - m * (1.0f / 25.0f);
    }
}

// ---- packed f32x2 helpers ----
__device__ __forceinline__ ull pack2(float lo, float hi) {
    ull d; asm("mov.b64 %0, {%1, %2};" : "=l"(d) : "f"(lo), "f"(hi)); return d;
}
__device__ __forceinline__ void unpack2(ull d, float& lo, float& hi) {
    asm("mov.b64 {%0, %1}, %2;" : "=f"(lo), "=f"(hi) : "l"(d));
}
__device__ __forceinline__ ull fma2(ull a, ull b, ull c) {
    ull d; asm("fma.rn.f32x2 %0, %1, %2, %3;" : "=l"(d) : "l"(a), "l"(b), "l"(c)); return d;
}
__device__ __forceinline__ ull mul2(ull a, ull b) {
    ull d; asm("mul.rn.f32x2 %0, %1, %2;" : "=l"(d) : "l"(a), "l"(b)); return d;
}
__device__ __forceinline__ ull add2(ull a, ull b) {
    ull d; asm("add.rn.f32x2 %0, %1, %2;" : "=l"(d) : "l"(a), "l"(b)); return d;
}
// packed leaky_relu: 0.505*x + 0.495*|x|  (== x for x>0, 0.01x for x<0)
__device__ __forceinline__ ull lrelu2(ull x, ull c505, ull c495) {
    ull ax = x & 0x7FFFFFFF7FFFFFFFULL;
    return fma2(ax, c495, mul2(x, c505));
}
// scalar leaky_relu; fabsf folds into the FFMA operand modifier -> 2 instrs
__device__ __forceinline__ float lrelu(float x) {
    return fmaf(0.495f, fabsf(x), 0.505f * x);
}
__device__ __forceinline__ float tanh_fast(float x) {
    float y;
    asm("tanh.approx.f32 %0, %1;" : "=f"(y) : "f"(x));
    return y;
}

__global__ __launch_bounds__(256, 3)
void ca_fused_kernel(const float* __restrict__ psi,
                     const float* __restrict__ bias1,
                     const float* __restrict__ w2,
                     const float* __restrict__ b2,
                     const float* __restrict__ w3,
                     const float* __restrict__ b3,
                     float* __restrict__ out)
{
    extern __shared__ __align__(16) float sm[];
    float* sp   = sm;                      // planar psi tile, pixel x at col x+2
    float* swt  = sm + OFF_SWT;            // conv weights: [(ch*5+r)*8 + dx], dx<5 valid
    ull*   sw2b = (ull*)(sm + OFF_SW2B);   // [i*8+o] = (w2[o][i], w2[o][i])
    ull*   sw3b = (ull*)(sm + OFF_SW3B);   // [i*8+o] = (w3[o][i], w3[o][i])
    float* sb1  = sm + OFF_SB1;            // 8
    ull*   sb2p = (ull*)(sm + OFF_SB2P);   // [o] = (b2[o], b2[o])
    ull*   sb3p = (ull*)(sm + OFF_SB3P);   // [o] = (b3[o], b3[o])

    const int tid = threadIdx.x;
    const int b   = blockIdx.y;
    const int y0  = blockIdx.x * TILE_H;

    // ---- stage params (strided: 320 slots > 256 threads) ----
    for (int k = tid; k < 320; k += 256) {
        int cr = k >> 3, dx = k & 7;       // cr = ch*5 + r
        int ch = cr / 5, r = cr % 5;
        swt[k] = (dx < 5) ? g_w[ch * 25 + r * 5 + dx] : 0.f;
    }
    if (tid < 64) {
        int i = tid >> 3, o = tid & 7;
        float a2 = w2[o * 8 + i], a3 = w3[o * 8 + i];
        sw2b[tid] = pack2(a2, a2);
        sw3b[tid] = pack2(a3, a3);
    }
    if (tid < 8) {
        sb1[tid] = bias1[tid];
        float v2 = b2[tid], v3 = b3[tid];
        sb2p[tid] = pack2(v2, v2);
        sb3p[tid] = pack2(v3, v3);
    }

    // ---- zero the x-halo columns (cols 0,1,66,67) ----
    for (int k = tid; k < HIDDEN * SROWS * 4; k += 256) {
        int c  = k & 3;
        int rr = k >> 2;                    // ch*SROWS + r
        int col = (c < 2) ? c : (64 + c);   // 0,1,66,67
        sp[rr * SROW + col] = 0.f;
    }

    // ---- interior fill: float4 global loads, zero rows outside the image ----
    const float* pb = psi + (size_t)b * (HIDDEN * RES * RES);
    for (int k = tid; k < HIDDEN * SROWS * 16; k += 256) {
        int q  = k & 15;                     // float4 index within row
        int rr = k >> 4;                     // ch*SROWS + r
        int r  = rr % SROWS;
        int ch = rr / SROWS;
        int gy = y0 + r - 2;
        float4 v = make_float4(0.f, 0.f, 0.f, 0.f);
        if ((unsigned)gy < RES)
            v = *(const float4*)(pb + (ch * RES + gy) * RES + q * 4);
        float2* d = (float2*)(sp + rr * SROW + q * 4 + 2);   // col = x+2 (8B aligned)
        d[0] = make_float2(v.x, v.y);
        d[1] = make_float2(v.z, v.w);
    }
    __syncthreads();

    const ull C505 = pack2(0.505f, 0.505f);
    const ull C495 = pack2(0.495f, 0.495f);

    // Each thread: 4 x-pixels of ONE output row, all 8 channels.
    const int tx = tid & 15;
    const int ry = tid >> 4;     // output row within tile (0..15)
    const int x0 = tx << 2;      // output x base (0..60)

    // GEMM1 accumulators, pixel-pair packed; conv fused into the channel loop.
    ull z2[8][2];
    #pragma unroll
    for (int o = 0; o < 8; o++) { ull bv = sb2p[o]; z2[o][0] = bv; z2[o][1] = bv; }

    #pragma unroll
    for (int ch = 0; ch < 8; ch++) {
        float bv = sb1[ch];
        float a0 = bv, a1 = bv, a2 = bv, a3 = bv;

        const float* base = sp + (ch * SROWS + ry) * SROW + x0;  // col x0 == pixel x0-2
        const float* wch  = swt + ch * 40;
        #pragma unroll
        for (int r = 0; r < 5; r++) {
            float4 A = *(const float4*)(base + r * SROW);
            float4 B = *(const float4*)(base + r * SROW + 4);
            float4 W = *(const float4*)(wch + r * 8);
            float  w4 = wch[r * 8 + 4];
            a0 = fmaf(W.x, A.x, a0); a1 = fmaf(W.x, A.y, a1);
            a2 = fmaf(W.x, A.z, a2); a3 = fmaf(W.x, A.w, a3);
            a0 = fmaf(W.y, A.y, a0); a1 = fmaf(W.y, A.z, a1);
            a2 = fmaf(W.y, A.w, a2); a3 = fmaf(W.y, B.x, a3);
            a0 = fmaf(W.z, A.z, a0); a1 = fmaf(W.z, A.w, a1);
            a2 = fmaf(W.z, B.x, a2); a3 = fmaf(W.z, B.y, a3);
            a0 = fmaf(W.w, A.w, a0); a1 = fmaf(W.w, B.x, a1);
            a2 = fmaf(W.w, B.y, a2); a3 = fmaf(W.w, B.z, a3);
            a0 = fmaf(w4,  B.x, a0); a1 = fmaf(w4,  B.y, a1);
            a2 = fmaf(w4,  B.z, a2); a3 = fmaf(w4,  B.w, a3);
        }
        // leaky_relu + pack to pixel pairs
        ull v0 = pack2(lrelu(a0), lrelu(a1));
        ull v1 = pack2(lrelu(a2), lrelu(a3));

        // fused GEMM1 accumulation (packed): z2[o] += w2[o][ch] * v
        const ull* wrow = sw2b + ch * 8;
        #pragma unroll
        for (int o = 0; o < 8; o++) {
            ull w = wrow[o];
            z2[o][0] = fma2(w, v0, z2[o][0]);
            z2[o][1] = fma2(w, v1, z2[o][1]);
        }
    }

    // leaky_relu on z2 (packed)
    #pragma unroll
    for (int o = 0; o < 8; o++) {
        z2[o][0] = lrelu2(z2[o][0], C505, C495);
        z2[o][1] = lrelu2(z2[o][1], C505, C495);
    }

    // GEMM2 per output channel (only 2 live accumulators) + residual + tanh + store
    float* ob = out + (size_t)b * (HIDDEN * RES * RES);
    const int gy = y0 + ry;
    #pragma unroll
    for (int o = 0; o < 8; o++) {
        ull h0 = sb3p[o], h1 = h0;
        #pragma unroll
        for (int i = 0; i < 8; i++) {
            ull w = sw3b[i * 8 + o];
            h0 = fma2(w, z2[i][0], h0);
            h1 = fma2(w, z2[i][1], h1);
        }
        // residual psi from smem: col x0+2 is even -> 8B-aligned ull loads
        const ull* rp = (const ull*)(sp + (o * SROWS + ry + 2) * SROW + x0 + 2);
        h0 = add2(h0, rp[0]);
        h1 = add2(h1, rp[1]);
        float e0, e1, e2, e3;
        unpack2(h0, e0, e1);
        unpack2(h1, e2, e3);
        float4 res;
        res.x = tanh_fast(e0); res.y = tanh_fast(e1);
        res.z = tanh_fast(e2); res.w = tanh_fast(e3);
        *(float4*)(ob + (o * RES + gy) * RES + x0) = res;
    }
}

extern "C" void kernel_launch(void* const* d_in, const int* in_sizes, int n_in,
                              void* d_out, int out_size) {
    const float* psi     = (const float*)d_in[0];
    const float* filter1 = (const float*)d_in[1];
    const float* bias1   = (const float*)d_in[2];
    const float* w2      = (const float*)d_in[3];
    const float* b2      = (const float*)d_in[4];
    const float* w3      = (const float*)d_in[5];
    const float* b3      = (const float*)d_in[6];
    float* out = (float*)d_out;

    cudaFuncSetAttribute(ca_fused_kernel,
                         cudaFuncAttributeMaxDynamicSharedMemorySize, SMEM_BYTES);

    prep_weights_kernel<<<1, 256>>>(filter1);

    dim3 grid(RES / TILE_H, NBATCH);
    ca_fused_kernel<<<grid, 256, SMEM_BYTES>>>(psi, bias1, w2, b2, w3, b3, out);
}

// round 14
// speedup vs baseline: 1.4764x; 1.1399x over previous
#include <cuda_runtime.h>

#define HIDDEN 8
#define RES 64
#define NBATCH 2048
#define TILE_H 16
#define SROWS 20           // TILE_H + 4 halo rows
#define SROW 72            // padded smem row stride (floats): cols 0..67 used
#define SP_FLOATS (HIDDEN * SROWS * SROW)
#define SMEM_FLOATS (SP_FLOATS + 200 + 64 + 64 + 8 + 8 + 8)
#define SMEM_BYTES (SMEM_FLOATS * 4)

// D4-symmetrized, per-kernel-zero-mean 5x5 depthwise weights
__device__ float g_w[HIDDEN * 25];

__global__ void prep_weights_kernel(const float* __restrict__ filter1) {
    __shared__ float sw[HIDDEN * 25];
    int t = threadIdx.x;
    float wv = 0.f;
    int h = 0;
    if (t < 200) {
        h = t / 25;
        int idx = t % 25;
        int i = idx / 5, j = idx % 5;
        const float* f = filter1 + h * 25;
        float s = f[i*5 + j] + f[(4-i)*5 + j] + f[i*5 + (4-j)] + f[(4-i)*5 + (4-j)]
                + f[j*5 + i] + f[(4-j)*5 + i] + f[j*5 + (4-i)] + f[(4-j)*5 + (4-i)];
        wv = 0.125f * s;
        sw[t] = wv;
    }
    __syncthreads();
    if (t < 200) {
        float m = 0.f;
        #pragma unroll
        for (int k = 0; k < 25; k++) m += sw[h * 25 + k];
        g_w[t] = wv - m * (1.0f / 25.0f);
    }
}

// 2-op leaky_relu: FMUL + FFMA (|x| folds into the FFMA operand modifier).
// 0.505*x + 0.495*|x| == x (x>0), 0.01x (x<0); 0.505f+0.495f == 1.0f exactly.
__device__ __forceinline__ float lrelu(float x) {
    return fmaf(0.495f, fabsf(x), 0.505f * x);
}
__device__ __forceinline__ float tanh_fast(float x) {
    float y;
    asm("tanh.approx.f32 %0, %1;" : "=f"(y) : "f"(x));
    return y;
}

__global__ __launch_bounds__(256, 3)
void ca_fused_kernel(const float* __restrict__ psi,
                     const float* __restrict__ bias1,
                     const float* __restrict__ w2,
                     const float* __restrict__ b2,
                     const float* __restrict__ w3,
                     const float* __restrict__ b3,
                     float* __restrict__ out)
{
    extern __shared__ __align__(16) float sm[];
    float* sp  = sm;                 // planar psi tile, pixel x at col x+2
    float* swt = sm + SP_FLOATS;     // 200 conv weights
    float* sw2 = swt + 200;          // 64 (transposed: sw2[i*8+o] = w2[o][i])
    float* sw3 = sw2 + 64;           // 64 (row-major: sw3[o*8+i])
    float* sb1 = sw3 + 64;           // 8
    float* sb2 = sb1 + 8;            // 8
    float* sb3 = sb2 + 8;            // 8

    const int tid = threadIdx.x;
    const int b   = blockIdx.y;
    const int y0  = blockIdx.x * TILE_H;

    // ---- stage small params into smem ----
    if (tid < 200) swt[tid] = g_w[tid];
    if (tid < 64) {
        int o = tid >> 3, i = tid & 7;
        sw2[i * 8 + o] = w2[tid];
    } else if (tid < 128)       sw3[tid - 64]  = w3[tid - 64];
    else if (tid < 136)         sb1[tid - 128] = bias1[tid - 128];
    else if (tid < 144)         sb2[tid - 136] = b2[tid - 136];
    else if (tid < 152)         sb3[tid - 144] = b3[tid - 144];

    // ---- zero the x-halo columns (cols 0,1,66,67) ----
    for (int k = tid; k < HIDDEN * SROWS * 4; k += 256) {
        int c  = k & 3;
        int rr = k >> 2;                    // ch*SROWS + r
        int col = (c < 2) ? c : (64 + c);   // 0,1,66,67
        sp[rr * SROW + col] = 0.f;
    }

    // ---- interior fill: float4 global loads, zero rows outside the image ----
    const float* pb = psi + (size_t)b * (HIDDEN * RES * RES);
    for (int k = tid; k < HIDDEN * SROWS * 16; k += 256) {
        int q  = k & 15;                     // float4 index within row
        int rr = k >> 4;                     // ch*SROWS + r
        int r  = rr % SROWS;
        int ch = rr / SROWS;
        int gy = y0 + r - 2;
        float4 v = make_float4(0.f, 0.f, 0.f, 0.f);
        if ((unsigned)gy < RES)
            v = *(const float4*)(pb + (ch * RES + gy) * RES + q * 4);
        float2* d = (float2*)(sp + rr * SROW + q * 4 + 2);   // col = x+2 (8B aligned)
        d[0] = make_float2(v.x, v.y);
        d[1] = make_float2(v.z, v.w);
    }
    __syncthreads();

    // Each thread: 4 x-pixels (x0..x0+3) of ONE output row (ry), all 8 channels.
    const int tx = tid & 15;
    const int ry = tid >> 4;     // output row within tile (0..15)
    const int x0 = tx << 2;      // output x base (0..60)

    // GEMM1 accumulators; conv fused into the channel loop so z never stores.
    float z2[8][4];
    #pragma unroll
    for (int o = 0; o < 8; o++) {
        float bv = sb2[o];
        z2[o][0] = bv; z2[o][1] = bv; z2[o][2] = bv; z2[o][3] = bv;
    }

    #pragma unroll
    for (int ch = 0; ch < 8; ch++) {
        float w[25];
        #pragma unroll
        for (int k = 0; k < 25; k++) w[k] = swt[ch * 25 + k];

        float bv = sb1[ch];
        float a0 = bv, a1 = bv, a2 = bv, a3 = bv;

        const float* base = sp + (ch * SROWS + ry) * SROW + x0;  // col x0 == pixel x0-2
        #pragma unroll
        for (int r = 0; r < 5; r++) {
            float4 A = *(const float4*)(base + r * SROW);
            float4 B = *(const float4*)(base + r * SROW + 4);
            float wv[8] = {A.x, A.y, A.z, A.w, B.x, B.y, B.z, B.w};
            #pragma unroll
            for (int dx = 0; dx < 5; dx++) {
                float ww = w[r * 5 + dx];
                a0 = fmaf(ww, wv[dx + 0], a0);
                a1 = fmaf(ww, wv[dx + 1], a1);
                a2 = fmaf(ww, wv[dx + 2], a2);
                a3 = fmaf(ww, wv[dx + 3], a3);
            }
        }
        float v0 = lrelu(a0), v1 = lrelu(a1), v2 = lrelu(a2), v3 = lrelu(a3);

        // fused GEMM1 accumulation: z2[o] += w2[o][ch] * v
        #pragma unroll
        for (int o = 0; o < 8; o++) {
            float ww = sw2[ch * 8 + o];
            z2[o][0] = fmaf(ww, v0, z2[o][0]);
            z2[o][1] = fmaf(ww, v1, z2[o][1]);
            z2[o][2] = fmaf(ww, v2, z2[o][2]);
            z2[o][3] = fmaf(ww, v3, z2[o][3]);
        }
    }

    // leaky_relu on z2
    #pragma unroll
    for (int o = 0; o < 8; o++) {
        z2[o][0] = lrelu(z2[o][0]);
        z2[o][1] = lrelu(z2[o][1]);
        z2[o][2] = lrelu(z2[o][2]);
        z2[o][3] = lrelu(z2[o][3]);
    }

    // GEMM2 per output channel (4 live accumulators) + residual (global, L1-hot)
    // + tanh + store
    float* ob = out + (size_t)b * (HIDDEN * RES * RES);
    const int gy = y0 + ry;
    #pragma unroll
    for (int o = 0; o < 8; o++) {
        float h0 = sb3[o], h1 = h0, h2 = h0, h3 = h0;
        #pragma unroll
        for (int i = 0; i < 8; i++) {
            float ww = sw3[o * 8 + i];
            h0 = fmaf(ww, z2[i][0], h0);
            h1 = fmaf(ww, z2[i][1], h1);
            h2 = fmaf(ww, z2[i][2], h2);
            h3 = fmaf(ww, z2[i][3], h3);
        }
        // residual psi straight from global: this line was loaded into L1 by the
        // fill loop of this very block (L1 persists within a launch).
        float4 pv = *(const float4*)(pb + (o * RES + gy) * RES + x0);
        float4 res;
        res.x = tanh_fast(pv.x + h0);
        res.y = tanh_fast(pv.y + h1);
        res.z = tanh_fast(pv.z + h2);
        res.w = tanh_fast(pv.w + h3);
        *(float4*)(ob + (o * RES + gy) * RES + x0) = res;
    }
}

extern "C" void kernel_launch(void* const* d_in, const int* in_sizes, int n_in,
                              void* d_out, int out_size) {
    const float* psi     = (const float*)d_in[0];
    const float* filter1 = (const float*)d_in[1];
    const float* bias1   = (const float*)d_in[2];
    const float* w2      = (const float*)d_in[3];
    const float* b2      = (const float*)d_in[4];
    const float* w3      = (const float*)d_in[5];
    const float* b3      = (const float*)d_in[6];
    float* out = (float*)d_out;

    cudaFuncSetAttribute(ca_fused_kernel,
                         cudaFuncAttributeMaxDynamicSharedMemorySize, SMEM_BYTES);

    prep_weights_kernel<<<1, 256>>>(filter1);

    dim3 grid(RES / TILE_H, NBATCH);
    ca_fused_kernel<<<grid, 256, SMEM_BYTES>>>(psi, bias1, w2, b2, w3, b3, out);
}

// round 15
// speedup vs baseline: 1.5010x; 1.0167x over previous
#include <cuda_runtime.h>

#define HIDDEN 8
#define RES 64
#define NBATCH 2048
#define TILE_H 16
#define SROWS 20           // TILE_H + 4 halo rows
#define SROW 72            // padded smem row stride (floats): cols 0..67 used
#define SP_FLOATS (HIDDEN * SROWS * SROW)
// conv weights stored as 3 symmetric rows x 5 taps, padded to 16/channel = 128
#define SMEM_FLOATS (SP_FLOATS + 128 + 64 + 64 + 8 + 8 + 8)
#define SMEM_BYTES (SMEM_FLOATS * 4)

// D4-symmetrized, per-kernel-zero-mean 5x5 depthwise weights
__device__ float g_w[HIDDEN * 25];

__global__ void prep_weights_kernel(const float* __restrict__ filter1) {
    __shared__ float sw[HIDDEN * 25];
    int t = threadIdx.x;
    float wv = 0.f;
    int h = 0;
    if (t < 200) {
        h = t / 25;
        int idx = t % 25;
        int i = idx / 5, j = idx % 5;
        const float* f = filter1 + h * 25;
        float s = f[i*5 + j] + f[(4-i)*5 + j] + f[i*5 + (4-j)] + f[(4-i)*5 + (4-j)]
                + f[j*5 + i] + f[(4-j)*5 + i] + f[j*5 + (4-i)] + f[(4-j)*5 + (4-i)];
        wv = 0.125f * s;
        sw[t] = wv;
    }
    __syncthreads();
    if (t < 200) {
        float m = 0.f;
        #pragma unroll
        for (int k = 0; k < 25; k++) m += sw[h * 25 + k];
        g_w[t] = wv - m * (1.0f / 25.0f);
    }
}

// 2-op leaky_relu: FMUL + FFMA (|x| folds into the FFMA operand modifier).
__device__ __forceinline__ float lrelu(float x) {
    return fmaf(0.495f, fabsf(x), 0.505f * x);
}
__device__ __forceinline__ float tanh_fast(float x) {
    float y;
    asm("tanh.approx.f32 %0, %1;" : "=f"(y) : "f"(x));
    return y;
}

__global__ __launch_bounds__(256, 3)
void ca_fused_kernel(const float* __restrict__ psi,
                     const float* __restrict__ bias1,
                     const float* __restrict__ w2,
                     const float* __restrict__ b2,
                     const float* __restrict__ w3,
                     const float* __restrict__ b3,
                     float* __restrict__ out)
{
    extern __shared__ __align__(16) float sm[];
    float* sp  = sm;                 // planar psi tile, pixel x at col x+2
    float* swt = sm + SP_FLOATS;     // conv weights: [ch*16 + r*5 + dx], r<3 (rows 3,4 mirror 1,0)
    float* sw2 = swt + 128;          // 64 (transposed: sw2[i*8+o] = w2[o][i])
    float* sw3 = sw2 + 64;           // 64 (row-major: sw3[o*8+i])
    float* sb1 = sw3 + 64;           // 8
    float* sb2 = sb1 + 8;            // 8
    float* sb3 = sb2 + 8;            // 8

    const int tid = threadIdx.x;
    const int b   = blockIdx.y;
    const int y0  = blockIdx.x * TILE_H;

    // ---- stage small params into smem ----
    // Conv weights: D4 symmetry guarantees row4==row0, row3==row1, so only
    // rows 0..2 are staged (15 weights/channel, padded to 16-slot stride).
    if (tid < 128) {
        int ch = tid >> 4, k = tid & 15;          // k = r*5+dx for k<15
        swt[tid] = (k < 15) ? g_w[ch * 25 + k] : 0.f;
    }
    if (tid < 64) {
        int o = tid >> 3, i = tid & 7;
        sw2[i * 8 + o] = w2[tid];
    } else if (tid < 128 + 64 && tid >= 128)  sw3[tid - 128] = w3[tid - 128];
    else if (tid >= 192 && tid < 200)         sb1[tid - 192] = bias1[tid - 192];
    else if (tid >= 200 && tid < 208)         sb2[tid - 200] = b2[tid - 200];
    else if (tid >= 208 && tid < 216)         sb3[tid - 208] = b3[tid - 208];

    // ---- zero the x-halo columns (cols 0,1,66,67) ----
    for (int k = tid; k < HIDDEN * SROWS * 4; k += 256) {
        int c  = k & 3;
        int rr = k >> 2;                    // ch*SROWS + r
        int col = (c < 2) ? c : (64 + c);   // 0,1,66,67
        sp[rr * SROW + col] = 0.f;
    }

    // ---- interior fill: float4 global loads, zero rows outside the image ----
    const float* pb = psi + (size_t)b * (HIDDEN * RES * RES);
    for (int k = tid; k < HIDDEN * SROWS * 16; k += 256) {
        int q  = k & 15;                     // float4 index within row
        int rr = k >> 4;                     // ch*SROWS + r
        int r  = rr % SROWS;
        int ch = rr / SROWS;
        int gy = y0 + r - 2;
        float4 v = make_float4(0.f, 0.f, 0.f, 0.f);
        if ((unsigned)gy < RES)
            v = *(const float4*)(pb + (ch * RES + gy) * RES + q * 4);
        float2* d = (float2*)(sp + rr * SROW + q * 4 + 2);   // col = x+2 (8B aligned)
        d[0] = make_float2(v.x, v.y);
        d[1] = make_float2(v.z, v.w);
    }
    __syncthreads();

    // Each thread: 4 x-pixels (x0..x0+3) of ONE output row (ry), all 8 channels.
    const int tx = tid & 15;
    const int ry = tid >> 4;     // output row within tile (0..15)
    const int x0 = tx << 2;      // output x base (0..60)

    // GEMM1 accumulators; conv fused into the channel loop so z never stores.
    float z2[8][4];
    #pragma unroll
    for (int o = 0; o < 8; o++) {
        float bv = sb2[o];
        z2[o][0] = bv; z2[o][1] = bv; z2[o][2] = bv; z2[o][3] = bv;
    }

    #pragma unroll
    for (int ch = 0; ch < 8; ch++) {
        float w[15];
        #pragma unroll
        for (int k = 0; k < 15; k++) w[k] = swt[ch * 16 + k];

        const float* base = sp + (ch * SROWS + ry) * SROW + x0;  // col x0 == pixel x0-2

        // Load the 5 window rows (8 wide) and fold by vertical symmetry:
        //   t0 = r0 + r4 (weight row 0), t1 = r1 + r3 (weight row 1), c2 = r2.
        float4 A0 = *(const float4*)(base + 0 * SROW), B0 = *(const float4*)(base + 0 * SROW + 4);
        float4 A1 = *(const float4*)(base + 1 * SROW), B1 = *(const float4*)(base + 1 * SROW + 4);
        float4 A2 = *(const float4*)(base + 2 * SROW), B2 = *(const float4*)(base + 2 * SROW + 4);
        float4 A3 = *(const float4*)(base + 3 * SROW), B3 = *(const float4*)(base + 3 * SROW + 4);
        float4 A4 = *(const float4*)(base + 4 * SROW), B4 = *(const float4*)(base + 4 * SROW + 4);

        float t0[8] = {A0.x + A4.x, A0.y + A4.y, A0.z + A4.z, A0.w + A4.w,
                       B0.x + B4.x, B0.y + B4.y, B0.z + B4.z, B0.w + B4.w};
        float t1[8] = {A1.x + A3.x, A1.y + A3.y, A1.z + A3.z, A1.w + A3.w,
                       B1.x + B3.x, B1.y + B3.y, B1.z + B3.z, B1.w + B3.w};
        float c2[8] = {A2.x, A2.y, A2.z, A2.w, B2.x, B2.y, B2.z, B2.w};

        float bv = sb1[ch];
        float a0 = bv, a1 = bv, a2 = bv, a3 = bv;
        #pragma unroll
        for (int dx = 0; dx < 5; dx++) {
            float w0 = w[dx], w1 = w[5 + dx], w2v = w[10 + dx];
            a0 = fmaf(w0, t0[dx + 0], a0);
            a1 = fmaf(w0, t0[dx + 1], a1);
            a2 = fmaf(w0, t0[dx + 2], a2);
            a3 = fmaf(w0, t0[dx + 3], a3);
            a0 = fmaf(w1, t1[dx + 0], a0);
            a1 = fmaf(w1, t1[dx + 1], a1);
            a2 = fmaf(w1, t1[dx + 2], a2);
            a3 = fmaf(w1, t1[dx + 3], a3);
            a0 = fmaf(w2v, c2[dx + 0], a0);
            a1 = fmaf(w2v, c2[dx + 1], a1);
            a2 = fmaf(w2v, c2[dx + 2], a2);
            a3 = fmaf(w2v, c2[dx + 3], a3);
        }
        float v0 = lrelu(a0), v1 = lrelu(a1), v2 = lrelu(a2), v3 = lrelu(a3);

        // fused GEMM1 accumulation: z2[o] += w2[o][ch] * v
        #pragma unroll
        for (int o = 0; o < 8; o++) {
            float ww = sw2[ch * 8 + o];
            z2[o][0] = fmaf(ww, v0, z2[o][0]);
            z2[o][1] = fmaf(ww, v1, z2[o][1]);
            z2[o][2] = fmaf(ww, v2, z2[o][2]);
            z2[o][3] = fmaf(ww, v3, z2[o][3]);
        }
    }

    // leaky_relu on z2
    #pragma unroll
    for (int o = 0; o < 8; o++) {
        z2[o][0] = lrelu(z2[o][0]);
        z2[o][1] = lrelu(z2[o][1]);
        z2[o][2] = lrelu(z2[o][2]);
        z2[o][3] = lrelu(z2[o][3]);
    }

    // GEMM2 per output channel (4 live accumulators) + residual (global, L1-hot)
    // + tanh + store
    float* ob = out + (size_t)b * (HIDDEN * RES * RES);
    const int gy = y0 + ry;
    #pragma unroll
    for (int o = 0; o < 8; o++) {
        float h0 = sb3[o], h1 = h0, h2 = h0, h3 = h0;
        #pragma unroll
        for (int i = 0; i < 8; i++) {
            float ww = sw3[o * 8 + i];
            h0 = fmaf(ww, z2[i][0], h0);
            h1 = fmaf(ww, z2[i][1], h1);
            h2 = fmaf(ww, z2[i][2], h2);
            h3 = fmaf(ww, z2[i][3], h3);
        }
        // residual psi straight from global (L1-hot from this block's fill loop)
        float4 pv = *(const float4*)(pb + (o * RES + gy) * RES + x0);
        float4 res;
        res.x = tanh_fast(pv.x + h0);
        res.y = tanh_fast(pv.y + h1);
        res.z = tanh_fast(pv.z + h2);
        res.w = tanh_fast(pv.w + h3);
        *(float4*)(ob + (o * RES + gy) * RES + x0) = res;
    }
}

extern "C" void kernel_launch(void* const* d_in, const int* in_sizes, int n_in,
                              void* d_out, int out_size) {
    const float* psi     = (const float*)d_in[0];
    const float* filter1 = (const float*)d_in[1];
    const float* bias1   = (const float*)d_in[2];
    const float* w2      = (const float*)d_in[3];
    const float* b2      = (const float*)d_in[4];
    const float* w3      = (const float*)d_in[5];
    const float* b3      = (const float*)d_in[6];
    float* out = (float*)d_out;

    cudaFuncSetAttribute(ca_fused_kernel,
                         cudaFuncAttributeMaxDynamicSharedMemorySize, SMEM_BYTES);

    prep_weights_kernel<<<1, 256>>>(filter1);

    dim3 grid(RES / TILE_H, NBATCH);
    ca_fused_kernel<<<grid, 256, SMEM_BYTES>>>(psi, bias1, w2, b2, w3, b3, out);
}

// round 16
// speedup vs baseline: 1.7048x; 1.1357x over previous
#include <cuda_runtime.h>

#define HIDDEN 8
#define RES 64
#define NBATCH 2048
#define TILE_H 16
#define SROWS 20           // TILE_H + 4 halo rows
#define SROW 72            // padded smem row stride (floats): cols 0..67 used
#define SP_FLOATS (HIDDEN * SROWS * SROW)
// conv weights stored as 3 symmetric rows x 5 taps, padded to 16/channel = 128
#define SMEM_FLOATS (SP_FLOATS + 128 + 64 + 64 + 8 + 8 + 8)
#define SMEM_BYTES (SMEM_FLOATS * 4)

// D4-symmetrized, per-kernel-zero-mean 5x5 depthwise weights
__device__ float g_w[HIDDEN * 25];

__global__ void prep_weights_kernel(const float* __restrict__ filter1) {
    __shared__ float sw[HIDDEN * 25];
    int t = threadIdx.x;
    float wv = 0.f;
    int h = 0;
    if (t < 200) {
        h = t / 25;
        int idx = t % 25;
        int i = idx / 5, j = idx % 5;
        const float* f = filter1 + h * 25;
        float s = f[i*5 + j] + f[(4-i)*5 + j] + f[i*5 + (4-j)] + f[(4-i)*5 + (4-j)]
                + f[j*5 + i] + f[(4-j)*5 + i] + f[j*5 + (4-i)] + f[(4-j)*5 + (4-i)];
        wv = 0.125f * s;
        sw[t] = wv;
    }
    __syncthreads();
    if (t < 200) {
        float m = 0.f;
        #pragma unroll
        for (int k = 0; k < 25; k++) m += sw[h * 25 + k];
        g_w[t] = wv - m * (1.0f / 25.0f);
    }
}

// 2-op leaky_relu: FMUL + FFMA (|x| folds into the FFMA operand modifier).
__device__ __forceinline__ float lrelu(float x) {
    return fmaf(0.495f, fabsf(x), 0.505f * x);
}
__device__ __forceinline__ float tanh_fast(float x) {
    float y;
    asm("tanh.approx.f32 %0, %1;" : "=f"(y) : "f"(x));
    return y;
}

__global__ __launch_bounds__(256, 4)
void ca_fused_kernel(const float* __restrict__ psi,
                     const float* __restrict__ bias1,
                     const float* __restrict__ w2,
                     const float* __restrict__ b2,
                     const float* __restrict__ w3,
                     const float* __restrict__ b3,
                     float* __restrict__ out)
{
    extern __shared__ __align__(16) float sm[];
    float* sp  = sm;                 // planar psi tile, pixel x at col x+2
    float* swt = sm + SP_FLOATS;     // conv weights: [ch*16 + r*5 + dx], r<3
    float* sw2 = swt + 128;          // 64 (transposed: sw2[i*8+o] = w2[o][i])
    float* sw3 = sw2 + 64;           // 64 (row-major: sw3[o*8+i])
    float* sb1 = sw3 + 64;           // 8
    float* sb2 = sb1 + 8;            // 8
    float* sb3 = sb2 + 8;            // 8

    const int tid = threadIdx.x;
    const int b   = blockIdx.y;
    const int y0  = blockIdx.x * TILE_H;

    // ---- stage small params into smem ----
    if (tid < 128) {
        int ch = tid >> 4, k = tid & 15;          // k = r*5+dx for k<15
        swt[tid] = (k < 15) ? g_w[ch * 25 + k] : 0.f;
    }
    if (tid < 64) {
        int o = tid >> 3, i = tid & 7;
        sw2[i * 8 + o] = w2[tid];
    } else if (tid >= 128 && tid < 192)  sw3[tid - 128] = w3[tid - 128];
    else if (tid >= 192 && tid < 200)    sb1[tid - 192] = bias1[tid - 192];
    else if (tid >= 200 && tid < 208)    sb2[tid - 200] = b2[tid - 200];
    else if (tid >= 208 && tid < 216)    sb3[tid - 208] = b3[tid - 208];

    // ---- zero the x-halo columns (cols 0,1,66,67) ----
    for (int k = tid; k < HIDDEN * SROWS * 4; k += 256) {
        int c  = k & 3;
        int rr = k >> 2;                    // ch*SROWS + r
        int col = (c < 2) ? c : (64 + c);   // 0,1,66,67
        sp[rr * SROW + col] = 0.f;
    }

    // ---- interior fill: float4 global loads, zero rows outside the image ----
    const float* pb = psi + (size_t)b * (HIDDEN * RES * RES);
    for (int k = tid; k < HIDDEN * SROWS * 16; k += 256) {
        int q  = k & 15;                     // float4 index within row
        int rr = k >> 4;                     // ch*SROWS + r
        int r  = rr % SROWS;
        int ch = rr / SROWS;
        int gy = y0 + r - 2;
        float4 v = make_float4(0.f, 0.f, 0.f, 0.f);
        if ((unsigned)gy < RES)
            v = *(const float4*)(pb + (ch * RES + gy) * RES + q * 4);
        float2* d = (float2*)(sp + rr * SROW + q * 4 + 2);   // col = x+2 (8B aligned)
        d[0] = make_float2(v.x, v.y);
        d[1] = make_float2(v.z, v.w);
    }
    __syncthreads();

    // Each thread: 4 x-pixels (x0..x0+3) of ONE output row (ry), all 8 channels.
    const int tx = tid & 15;
    const int ry = tid >> 4;     // output row within tile (0..15)
    const int x0 = tx << 2;      // output x base (0..60)

    // GEMM1 accumulators; conv fused into the channel loop so z never stores.
    float z2[8][4];
    #pragma unroll
    for (int o = 0; o < 8; o++) {
        float bv = sb2[o];
        z2[o][0] = bv; z2[o][1] = bv; z2[o][2] = bv; z2[o][3] = bv;
    }

    #pragma unroll
    for (int ch = 0; ch < 8; ch++) {
        const float* base = sp + (ch * SROWS + ry) * SROW + x0;  // col x0 == pixel x0-2
        const float* wch  = swt + ch * 16;

        float bv = sb1[ch];
        float a0 = bv, a1 = bv, a2 = bv, a3 = bv;

        // Row-pair at a time (register-lean): vertical symmetry row4==row0,
        // row3==row1. Fold each pair immediately, then 5 taps x 4 px.
        #pragma unroll
        for (int r = 0; r < 3; r++) {
            float4 A = *(const float4*)(base + r * SROW);
            float4 B = *(const float4*)(base + r * SROW + 4);
            float t[8];
            if (r < 2) {
                float4 C = *(const float4*)(base + (4 - r) * SROW);
                float4 D = *(const float4*)(base + (4 - r) * SROW + 4);
                t[0] = A.x + C.x; t[1] = A.y + C.y; t[2] = A.z + C.z; t[3] = A.w + C.w;
                t[4] = B.x + D.x; t[5] = B.y + D.y; t[6] = B.z + D.z; t[7] = B.w + D.w;
            } else {
                t[0] = A.x; t[1] = A.y; t[2] = A.z; t[3] = A.w;
                t[4] = B.x; t[5] = B.y; t[6] = B.z; t[7] = B.w;
            }
            #pragma unroll
            for (int dx = 0; dx < 5; dx++) {
                float ww = wch[r * 5 + dx];      // broadcast LDS, no resident array
                a0 = fmaf(ww, t[dx + 0], a0);
                a1 = fmaf(ww, t[dx + 1], a1);
                a2 = fmaf(ww, t[dx + 2], a2);
                a3 = fmaf(ww, t[dx + 3], a3);
            }
        }
        float v0 = lrelu(a0), v1 = lrelu(a1), v2 = lrelu(a2), v3 = lrelu(a3);

        // fused GEMM1 accumulation: z2[o] += w2[o][ch] * v
        #pragma unroll
        for (int o = 0; o < 8; o++) {
            float ww = sw2[ch * 8 + o];
            z2[o][0] = fmaf(ww, v0, z2[o][0]);
            z2[o][1] = fmaf(ww, v1, z2[o][1]);
            z2[o][2] = fmaf(ww, v2, z2[o][2]);
            z2[o][3] = fmaf(ww, v3, z2[o][3]);
        }
    }

    // leaky_relu on z2
    #pragma unroll
    for (int o = 0; o < 8; o++) {
        z2[o][0] = lrelu(z2[o][0]);
        z2[o][1] = lrelu(z2[o][1]);
        z2[o][2] = lrelu(z2[o][2]);
        z2[o][3] = lrelu(z2[o][3]);
    }

    // GEMM2 per output channel (4 live accumulators) + residual (global, L1-hot)
    // + tanh + store
    float* ob = out + (size_t)b * (HIDDEN * RES * RES);
    const int gy = y0 + ry;
    #pragma unroll
    for (int o = 0; o < 8; o++) {
        float h0 = sb3[o], h1 = h0, h2 = h0, h3 = h0;
        #pragma unroll
        for (int i = 0; i < 8; i++) {
            float ww = sw3[o * 8 + i];
            h0 = fmaf(ww, z2[i][0], h0);
            h1 = fmaf(ww, z2[i][1], h1);
            h2 = fmaf(ww, z2[i][2], h2);
            h3 = fmaf(ww, z2[i][3], h3);
        }
        float4 pv = *(const float4*)(pb + (o * RES + gy) * RES + x0);
        float4 res;
        res.x = tanh_fast(pv.x + h0);
        res.y = tanh_fast(pv.y + h1);
        res.z = tanh_fast(pv.z + h2);
        res.w = tanh_fast(pv.w + h3);
        *(float4*)(ob + (o * RES + gy) * RES + x0) = res;
    }
}

extern "C" void kernel_launch(void* const* d_in, const int* in_sizes, int n_in,
                              void* d_out, int out_size) {
    const float* psi     = (const float*)d_in[0];
    const float* filter1 = (const float*)d_in[1];
    const float* bias1   = (const float*)d_in[2];
    const float* w2      = (const float*)d_in[3];
    const float* b2      = (const float*)d_in[4];
    const float* w3      = (const float*)d_in[5];
    const float* b3      = (const float*)d_in[6];
    float* out = (float*)d_out;

    cudaFuncSetAttribute(ca_fused_kernel,
                         cudaFuncAttributeMaxDynamicSharedMemorySize, SMEM_BYTES);

    prep_weights_kernel<<<1, 256>>>(filter1);

    dim3 grid(RES / TILE_H, NBATCH);
    ca_fused_kernel<<<grid, 256, SMEM_BYTES>>>(psi, bias1, w2, b2, w3, b3, out);
}